// round 13
// baseline (speedup 1.0000x reference)
#include <cuda_runtime.h>
#include <cuda_bf16.h>
#include <math.h>

// Problem constants (fixed by the dataset)
#define N_NODES   100000
#define N_EDGES   1600000
#define IN_FEATS  128
#define HD        64          // NUM_HEADS * OUT_FEATS = 4*16
#define NUM_HEADS 4
#define OUT_FEATS 16
#define EDGE_FEATS 32
#define NUM_ETYPES 8
#define NEG_SLOPE 0.2f

#define SBLK  512
#define NSBLK ((N_NODES + SBLK - 1) / SBLK)   // 196
#define E4    (N_EDGES / 4)                    // 400000 int4 groups
#define E4_BLOCKS ((E4 + 255) / 256)           // ceil-div grid
#define FBLK  128                              // nodes per feat block
#define NFBLK ((N_NODES + FBLK - 1) / FBLK)    // 782
#define FEAT_SPLIT 650                         // blocks on main stream

// feat_kernel dynamic smem layout (floats): xs + wt  (96 KB)
#define FEAT_SMEM_FLOATS (FBLK * IN_FEATS + IN_FEATS * HD)
#define FEAT_SMEM_BYTES  (FEAT_SMEM_FLOATS * 4)

// ---------------- static device scratch (no allocations allowed) -------------
__device__ __align__(16) float  g_feat[N_NODES * HD];     // projected features [N,64]
__device__ __align__(16) float  g_el[N_NODES * NUM_HEADS];
__device__ __align__(16) float  g_er[N_NODES * NUM_HEADS];
__device__ __align__(16) float  g_ee[NUM_ETYPES * NUM_HEADS];  // [et][h]
__device__ __align__(16) float  g_wl[8][IN_FEATS];        // folded attn weights
__device__ int    g_count[N_NODES];
__device__ int    g_off[N_NODES + 1];
__device__ int    g_cursor[N_NODES];
__device__ __align__(8) int2   g_edge[N_EDGES];           // (src|et<<17, dst), CSR order
__device__ __align__(16) float4 g_ex[N_EDGES];            // exp(logit) per edge, CSR order
__device__ int    g_bsum[NSBLK];

// ---------------- K_wl: fold attn_l/attn_r into fc_w (128x8) + ee table -----
// blocks 0-3: wl entries. block 4: ee table.
__global__ void wl_kernel(const float* __restrict__ fc_w,
                          const float* __restrict__ attn_l,
                          const float* __restrict__ attn_r,
                          const float* __restrict__ edge_emb,
                          const float* __restrict__ fc_e_w,
                          const float* __restrict__ attn_e) {
    if (blockIdx.x < 4) {
        int gid = blockIdx.x * 256 + threadIdx.x;   // [0,1024)
        int c = gid >> 7, k = gid & 127;
        int h = c & 3;
        const float* av = (c >= 4) ? attn_r : attn_l;
        float s = 0.f;
        #pragma unroll
        for (int d = 0; d < OUT_FEATS; d++)
            s += fc_w[(h * OUT_FEATS + d) * IN_FEATS + k] * av[h * OUT_FEATS + d];
        g_wl[c][k] = s;
    } else if (threadIdx.x < NUM_ETYPES * NUM_HEADS) {
        int t  = threadIdx.x;
        int et = t & (NUM_ETYPES - 1);
        int h  = t >> 3;
        const float* emb = edge_emb + et * EDGE_FEATS;
        float s = 0.f;
        for (int fe = 0; fe < EDGE_FEATS; fe++) {
            const float* wrow = fc_e_w + (h * EDGE_FEATS + fe) * EDGE_FEATS;
            float proj = 0.f;
            #pragma unroll 8
            for (int j = 0; j < EDGE_FEATS; j++) proj += emb[j] * wrow[j];
            s += proj * attn_e[h * EDGE_FEATS + fe];
        }
        g_ee[et * NUM_HEADS + h] = s;
    }
}

// ---------------- K_elr: el/er = x @ wl (one warp per node) ------------------
__global__ __launch_bounds__(256) void el_er_kernel(const float* __restrict__ x) {
    int warp = threadIdx.x >> 5, lane = threadIdx.x & 31;
    float4 w[8];
    #pragma unroll
    for (int c = 0; c < 8; c++)
        w[c] = __ldg(((const float4*)&g_wl[c][0]) + lane);

    for (int n = blockIdx.x * 8 + warp; n < N_NODES; n += gridDim.x * 8) {
        float4 xv = __ldg((const float4*)(x + (size_t)n * IN_FEATS) + lane);
        float p[8];
        #pragma unroll
        for (int c = 0; c < 8; c++)
            p[c] = xv.x * w[c].x + xv.y * w[c].y + xv.z * w[c].z + xv.w * w[c].w;
        #pragma unroll
        for (int off = 16; off >= 1; off >>= 1)
            #pragma unroll
            for (int c = 0; c < 8; c++)
                p[c] += __shfl_xor_sync(0xFFFFFFFFu, p[c], off);
        if (lane == 0) {
            ((float4*)g_el)[n] = make_float4(p[0], p[1], p[2], p[3]);
            ((float4*)g_er)[n] = make_float4(p[4], p[5], p[6], p[7]);
        }
    }
}

// ---------------- K1: histogram of dst (4 edges/thread, int4 loads) ---------
__global__ void hist_kernel(const int* __restrict__ dst) {
    int t = blockIdx.x * blockDim.x + threadIdx.x;
    if (t >= E4) return;
    int4 d = ((const int4*)dst)[t];
    atomicAdd(&g_count[d.x], 1);
    atomicAdd(&g_count[d.y], 1);
    atomicAdd(&g_count[d.z], 1);
    atomicAdd(&g_count[d.w], 1);
}

// ---------------- K2a: per-block inclusive scan of counts -------------------
__global__ __launch_bounds__(SBLK) void scan1_kernel() {
    __shared__ int sm[SBLK];
    int t = threadIdx.x;
    int i = blockIdx.x * SBLK + t;
    int c = (i < N_NODES) ? g_count[i] : 0;
    sm[t] = c;
    __syncthreads();
    #pragma unroll
    for (int off = 1; off < SBLK; off <<= 1) {
        int v = (t >= off) ? sm[t - off] : 0;
        __syncthreads();
        sm[t] += v;
        __syncthreads();
    }
    if (i < N_NODES) g_off[i] = sm[t] - c;     // block-local exclusive
    if (t == SBLK - 1) g_bsum[blockIdx.x] = sm[t];
}

// ---------------- K2b: merged scan of block sums + fix-up + cursor init -----
__global__ __launch_bounds__(SBLK) void scan23_kernel() {
    __shared__ int bs[SBLK];
    int t = threadIdx.x;
    int myb = g_bsum[blockIdx.x];              // read before smem scan
    bs[t] = (t < NSBLK) ? g_bsum[t] : 0;
    __syncthreads();
    #pragma unroll
    for (int off = 1; off < SBLK; off <<= 1) {
        int v = (t >= off) ? bs[t - off] : 0;
        __syncthreads();
        bs[t] += v;
        __syncthreads();
    }
    int prefix = bs[blockIdx.x] - myb;         // exclusive prefix of this block
    int i = blockIdx.x * SBLK + t;
    if (i < N_NODES) {
        int o = g_off[i] + prefix;
        g_off[i] = o;
        g_cursor[i] = o;
    }
    if (blockIdx.x == NSBLK - 1 && t == 0) g_off[N_NODES] = bs[NSBLK - 1];
}

// ---------------- K3: position-only scatter, one int2 STG.64 per edge -------
__global__ void scatter_lite_kernel(const int* __restrict__ src,
                                    const int* __restrict__ dst,
                                    const int* __restrict__ etype) {
    int t = blockIdx.x * blockDim.x + threadIdx.x;
    if (t >= E4) return;
    int4 s4  = ((const int4*)src)[t];
    int4 d4  = ((const int4*)dst)[t];
    int4 et4 = ((const int4*)etype)[t];
    int p;
    p = atomicAdd(&g_cursor[d4.x], 1); g_edge[p] = make_int2(s4.x | (et4.x << 17), d4.x);
    p = atomicAdd(&g_cursor[d4.y], 1); g_edge[p] = make_int2(s4.y | (et4.y << 17), d4.y);
    p = atomicAdd(&g_cursor[d4.z], 1); g_edge[p] = make_int2(s4.z | (et4.z << 17), d4.z);
    p = atomicAdd(&g_cursor[d4.w], 1); g_edge[p] = make_int2(s4.w | (et4.w << 17), d4.w);
}

// ---------------- K4: register-tiled SGEMM feat = x @ fc_w^T (pure GEMM) -----
__global__ __launch_bounds__(256) void feat_kernel(
        const float* __restrict__ x,
        const float* __restrict__ fc_w,
        int blk0) {
    extern __shared__ float smem[];
    float* xs = smem;                              // [FBLK][IN_FEATS]
    float* wt = smem + FBLK * IN_FEATS;            // [IN_FEATS][HD]

    int tid = threadIdx.x;
    int tx = tid & 15;
    int ty = tid >> 4;
    int blk = blockIdx.x + blk0;

    // load fc_w transposed: fc_w[j*128+k] -> wt[k*HD+j]
    for (int i = tid; i < HD * IN_FEATS; i += 256) {
        int j = i >> 7, k = i & 127;
        wt[k * HD + j] = fc_w[i];
    }

    // load 128 node rows, float4-coalesced; OOB nodes read row 0 (stores guarded)
    long long nbase = (long long)blk * FBLK;
    for (int i = tid; i < FBLK * (IN_FEATS / 4); i += 256) {
        int n = i >> 5, k4 = i & 31;
        long long gn = nbase + n;
        const float4* srcp = (const float4*)(x + (gn < N_NODES ? gn : 0) * IN_FEATS);
        ((float4*)(xs + n * IN_FEATS))[k4] = srcp[k4];
    }
    __syncthreads();

    float acc[8][4];
    #pragma unroll
    for (int i = 0; i < 8; i++)
        #pragma unroll
        for (int c = 0; c < 4; c++) acc[i][c] = 0.f;

    #pragma unroll 2
    for (int k4 = 0; k4 < IN_FEATS / 4; k4++) {
        float4 wv0 = *(const float4*)&wt[(k4 * 4 + 0) * HD + tx * 4];
        float4 wv1 = *(const float4*)&wt[(k4 * 4 + 1) * HD + tx * 4];
        float4 wv2 = *(const float4*)&wt[(k4 * 4 + 2) * HD + tx * 4];
        float4 wv3 = *(const float4*)&wt[(k4 * 4 + 3) * HD + tx * 4];
        #pragma unroll
        for (int i = 0; i < 8; i++) {
            float4 xv = ((const float4*)(xs + (ty * 8 + i) * IN_FEATS))[k4];
            acc[i][0] = fmaf(xv.x, wv0.x, acc[i][0]);
            acc[i][1] = fmaf(xv.x, wv0.y, acc[i][1]);
            acc[i][2] = fmaf(xv.x, wv0.z, acc[i][2]);
            acc[i][3] = fmaf(xv.x, wv0.w, acc[i][3]);
            acc[i][0] = fmaf(xv.y, wv1.x, acc[i][0]);
            acc[i][1] = fmaf(xv.y, wv1.y, acc[i][1]);
            acc[i][2] = fmaf(xv.y, wv1.z, acc[i][2]);
            acc[i][3] = fmaf(xv.y, wv1.w, acc[i][3]);
            acc[i][0] = fmaf(xv.z, wv2.x, acc[i][0]);
            acc[i][1] = fmaf(xv.z, wv2.y, acc[i][1]);
            acc[i][2] = fmaf(xv.z, wv2.z, acc[i][2]);
            acc[i][3] = fmaf(xv.z, wv2.w, acc[i][3]);
            acc[i][0] = fmaf(xv.w, wv3.x, acc[i][0]);
            acc[i][1] = fmaf(xv.w, wv3.y, acc[i][1]);
            acc[i][2] = fmaf(xv.w, wv3.z, acc[i][2]);
            acc[i][3] = fmaf(xv.w, wv3.w, acc[i][3]);
        }
    }

    #pragma unroll
    for (int i = 0; i < 8; i++) {
        long long n = nbase + ty * 8 + i;
        if (n < N_NODES)
            *(float4*)&g_feat[n * HD + tx * 4] =
                make_float4(acc[i][0], acc[i][1], acc[i][2], acc[i][3]);
    }
}

// ---------------- K_ex: edge-parallel exp(leaky(logit)) in CSR order ----------
__global__ __launch_bounds__(256) void ex_kernel() {
    __shared__ float see[NUM_ETYPES * NUM_HEADS];
    int tid = threadIdx.x;
    if (tid < NUM_ETYPES * NUM_HEADS) see[tid] = g_ee[tid];
    __syncthreads();

    int t = blockIdx.x * blockDim.x + tid;     // CSR edge index
    if (t >= N_EDGES) return;
    int2 e2 = g_edge[t];
    int s  = e2.x & 0x1FFFF;
    int et = e2.x >> 17;
    int d  = e2.y;
    float4 el = __ldg(((const float4*)g_el) + s);
    float4 er = __ldg(((const float4*)g_er) + d);
    float e0 = el.x + er.x + see[et * 4 + 0];
    float e1 = el.y + er.y + see[et * 4 + 1];
    float e2f = el.z + er.z + see[et * 4 + 2];
    float e3 = el.w + er.w + see[et * 4 + 3];
    e0 = e0 > 0.f ? e0 : NEG_SLOPE * e0;
    e1 = e1 > 0.f ? e1 : NEG_SLOPE * e1;
    e2f = e2f > 0.f ? e2f : NEG_SLOPE * e2f;
    e3 = e3 > 0.f ? e3 : NEG_SLOPE * e3;
    g_ex[t] = make_float4(__expf(e0), __expf(e1), __expf(e2f), __expf(e3));
}

// ---------------- K5: per-dst gather with fused denominator ------------------
__global__ __launch_bounds__(256) void aggregate_kernel(float* __restrict__ out) {
    int tid = threadIdx.x;
    int warp = tid >> 5, lane = tid & 31;
    int n = blockIdx.x * 8 + warp;
    if (n >= N_NODES) return;

    float2* out2 = (float2*)out;
    int beg = g_off[n];
    int deg = g_off[n + 1] - beg;
    if (deg == 0) {
        out2[n * 32 + lane] = make_float2(0.f, 0.f);
        return;
    }
    int hsel = lane >> 3;                    // head for this lane's 2 columns

    const float* exf = (const float*)(g_ex + beg);
    float denom = 0.f;
    float2 acc = make_float2(0.f, 0.f);
    int i = 0;
    for (; i + 8 <= deg; i += 8) {
        int s[8]; float p[8]; float2 f[8];
        #pragma unroll
        for (int j = 0; j < 8; j++) {
            s[j] = __ldg(&g_edge[beg + i + j].x) & 0x1FFFF;
            p[j] = __ldg(exf + (i + j) * 4 + hsel);
        }
        #pragma unroll
        for (int j = 0; j < 8; j++)
            f[j] = __ldg(((const float2*)(g_feat + s[j] * HD)) + lane);
        #pragma unroll
        for (int j = 0; j < 8; j++) {
            denom += p[j];
            acc.x = fmaf(p[j], f[j].x, acc.x);
            acc.y = fmaf(p[j], f[j].y, acc.y);
        }
    }
    for (; i < deg; i++) {
        int s   = __ldg(&g_edge[beg + i].x) & 0x1FFFF;
        float p = __ldg(exf + i * 4 + hsel);
        float2 f = __ldg(((const float2*)(g_feat + s * HD)) + lane);
        denom += p;
        acc.x = fmaf(p, f.x, acc.x);
        acc.y = fmaf(p, f.y, acc.y);
    }

    float inv = 1.f / denom;
    out2[n * 32 + lane] = make_float2(acc.x * inv, acc.y * inv);
}

// ---------------- launch ------------------------------------------------------
// main: wl -> el_er (record evLR) -> featA ............ wait evJoin -> aggregate
// side: memset/hist/scan1/scan23/scatter_lite -> wait evLR -> ex -> featB (evJoin)
extern "C" void kernel_launch(void* const* d_in, const int* in_sizes, int n_in,
                              void* d_out, int out_size) {
    const float* x        = (const float*)d_in[0];
    const int*   src      = (const int*)d_in[1];
    const int*   dst      = (const int*)d_in[2];
    const int*   etype    = (const int*)d_in[3];
    const float* fc_w     = (const float*)d_in[4];
    const float* fc_e_w   = (const float*)d_in[5];
    const float* edge_emb = (const float*)d_in[6];
    const float* attn_l   = (const float*)d_in[7];
    const float* attn_r   = (const float*)d_in[8];
    const float* attn_e   = (const float*)d_in[9];
    float* out = (float*)d_out;

    static bool attr_set = false;
    if (!attr_set) {
        cudaFuncSetAttribute(feat_kernel,
                             cudaFuncAttributeMaxDynamicSharedMemorySize,
                             FEAT_SMEM_BYTES);
        attr_set = true;
    }

    void* cntPtr = nullptr;
    cudaGetSymbolAddress(&cntPtr, g_count);

    cudaStream_t side = 0;
    cudaEvent_t evFork = 0, evLR = 0, evJoin = 0;
    bool forked =
        (cudaStreamCreateWithFlags(&side, cudaStreamNonBlocking) == cudaSuccess) &&
        (cudaEventCreateWithFlags(&evFork, cudaEventDisableTiming) == cudaSuccess) &&
        (cudaEventCreateWithFlags(&evLR, cudaEventDisableTiming) == cudaSuccess) &&
        (cudaEventCreateWithFlags(&evJoin, cudaEventDisableTiming) == cudaSuccess);

    if (forked && cudaEventRecord(evFork, 0) == cudaSuccess &&
        cudaStreamWaitEvent(side, evFork, 0) == cudaSuccess) {
        // side stream: CSR build
        cudaMemsetAsync(cntPtr, 0, N_NODES * sizeof(int), side);
        hist_kernel<<<E4_BLOCKS, 256, 0, side>>>(dst);
        scan1_kernel<<<NSBLK, SBLK, 0, side>>>();
        scan23_kernel<<<NSBLK, SBLK, 0, side>>>();
        scatter_lite_kernel<<<E4_BLOCKS, 256, 0, side>>>(src, dst, etype);
        // main stream: attn-folded weights + el/er, then bulk of the GEMM
        wl_kernel<<<5, 256>>>(fc_w, attn_l, attn_r, edge_emb, fc_e_w, attn_e);
        el_er_kernel<<<592, 256>>>(x);
        cudaEventRecord(evLR, 0);
        feat_kernel<<<FEAT_SPLIT, 256, FEAT_SMEM_BYTES>>>(x, fc_w, 0);
        // side stream: ex (needs el/er + scatter), then remainder of the GEMM
        cudaStreamWaitEvent(side, evLR, 0);
        ex_kernel<<<(N_EDGES + 255) / 256, 256, 0, side>>>();
        feat_kernel<<<NFBLK - FEAT_SPLIT, 256, FEAT_SMEM_BYTES, side>>>(x, fc_w, FEAT_SPLIT);
        cudaEventRecord(evJoin, side);
        cudaStreamWaitEvent(0, evJoin, 0);
    } else {
        // fallback: fully serial on capture stream
        cudaMemsetAsync(cntPtr, 0, N_NODES * sizeof(int), 0);
        hist_kernel<<<E4_BLOCKS, 256>>>(dst);
        scan1_kernel<<<NSBLK, SBLK>>>();
        scan23_kernel<<<NSBLK, SBLK>>>();
        scatter_lite_kernel<<<E4_BLOCKS, 256>>>(src, dst, etype);
        wl_kernel<<<5, 256>>>(fc_w, attn_l, attn_r, edge_emb, fc_e_w, attn_e);
        el_er_kernel<<<592, 256>>>(x);
        ex_kernel<<<(N_EDGES + 255) / 256, 256>>>();
        feat_kernel<<<NFBLK, 256, FEAT_SMEM_BYTES>>>(x, fc_w, 0);
        aggregate_kernel<<<(N_NODES + 7) / 8, 256>>>(out);
        if (side)   cudaStreamDestroy(side);
        if (evFork) cudaEventDestroy(evFork);
        if (evLR)   cudaEventDestroy(evLR);
        if (evJoin) cudaEventDestroy(evJoin);
        return;
    }

    aggregate_kernel<<<(N_NODES + 7) / 8, 256>>>(out);

    if (side)   cudaStreamDestroy(side);
    if (evFork) cudaEventDestroy(evFork);
    if (evLR)   cudaEventDestroy(evLR);
    if (evJoin) cudaEventDestroy(evJoin);
}

// round 15
// speedup vs baseline: 1.3159x; 1.3159x over previous
#include <cuda_runtime.h>
#include <cuda_bf16.h>
#include <math.h>

// Problem constants (fixed by the dataset)
#define N_NODES   100000
#define N_EDGES   1600000
#define IN_FEATS  128
#define HD        64          // NUM_HEADS * OUT_FEATS = 4*16
#define NUM_HEADS 4
#define OUT_FEATS 16
#define EDGE_FEATS 32
#define NUM_ETYPES 8
#define NEG_SLOPE 0.2f

#define SBLK  512
#define NSBLK ((N_NODES + SBLK - 1) / SBLK)   // 196
#define E4    (N_EDGES / 4)                    // 400000 int4 groups
#define E4_BLOCKS ((E4 + 255) / 256)           // ceil-div grid
#define FBLK  128                              // nodes per feat block
#define NFBLK ((N_NODES + FBLK - 1) / FBLK)    // 782

// feat_kernel dynamic smem layout (floats): xs + wt + al + ar
#define FEAT_SMEM_FLOATS (FBLK * IN_FEATS + IN_FEATS * HD + 2 * HD)
#define FEAT_SMEM_BYTES  (FEAT_SMEM_FLOATS * 4)

// ---------------- static device scratch (no allocations allowed) -------------
__device__ __align__(16) float  g_feat[N_NODES * HD];     // projected features [N,64]
__device__ __align__(16) float  g_el[N_NODES * NUM_HEADS];
__device__ __align__(16) float  g_er[N_NODES * NUM_HEADS];
__device__ __align__(16) float  g_ee[NUM_ETYPES * NUM_HEADS];  // [et][h]
__device__ int    g_count[N_NODES];
__device__ int    g_off[N_NODES + 1];
__device__ int    g_cursor[N_NODES];
__device__ __align__(8) int2   g_edge[N_EDGES];           // (src|et<<17, dst), CSR order
__device__ __align__(16) float4 g_ex[N_EDGES];            // exp(logit) per edge, CSR order
__device__ int    g_bsum[NSBLK];

// ---------------- K1: histogram of dst (4 edges/thread, int4 loads) ---------
__global__ void hist_kernel(const int* __restrict__ dst) {
    int t = blockIdx.x * blockDim.x + threadIdx.x;
    if (t >= E4) return;
    int4 d = ((const int4*)dst)[t];
    atomicAdd(&g_count[d.x], 1);
    atomicAdd(&g_count[d.y], 1);
    atomicAdd(&g_count[d.z], 1);
    atomicAdd(&g_count[d.w], 1);
}

// ---------------- K2a: per-block inclusive scan of counts -------------------
__global__ __launch_bounds__(SBLK) void scan1_kernel() {
    __shared__ int sm[SBLK];
    int t = threadIdx.x;
    int i = blockIdx.x * SBLK + t;
    int c = (i < N_NODES) ? g_count[i] : 0;
    sm[t] = c;
    __syncthreads();
    #pragma unroll
    for (int off = 1; off < SBLK; off <<= 1) {
        int v = (t >= off) ? sm[t - off] : 0;
        __syncthreads();
        sm[t] += v;
        __syncthreads();
    }
    if (i < N_NODES) g_off[i] = sm[t] - c;     // block-local exclusive
    if (t == SBLK - 1) g_bsum[blockIdx.x] = sm[t];
}

// ---------------- K2b: merged scan of block sums + fix-up + cursor init -----
__global__ __launch_bounds__(SBLK) void scan23_kernel() {
    __shared__ int bs[SBLK];
    int t = threadIdx.x;
    int myb = g_bsum[blockIdx.x];              // read before smem scan
    bs[t] = (t < NSBLK) ? g_bsum[t] : 0;
    __syncthreads();
    #pragma unroll
    for (int off = 1; off < SBLK; off <<= 1) {
        int v = (t >= off) ? bs[t - off] : 0;
        __syncthreads();
        bs[t] += v;
        __syncthreads();
    }
    int prefix = bs[blockIdx.x] - myb;         // exclusive prefix of this block
    int i = blockIdx.x * SBLK + t;
    if (i < N_NODES) {
        int o = g_off[i] + prefix;
        g_off[i] = o;
        g_cursor[i] = o;
    }
    if (blockIdx.x == NSBLK - 1 && t == 0) g_off[N_NODES] = bs[NSBLK - 1];
}

// ---------------- K3: position-only scatter, one int2 STG.64 per edge -------
__global__ void scatter_lite_kernel(const int* __restrict__ src,
                                    const int* __restrict__ dst,
                                    const int* __restrict__ etype) {
    int t = blockIdx.x * blockDim.x + threadIdx.x;
    if (t >= E4) return;
    int4 s4  = ((const int4*)src)[t];
    int4 d4  = ((const int4*)dst)[t];
    int4 et4 = ((const int4*)etype)[t];
    int p;
    p = atomicAdd(&g_cursor[d4.x], 1); g_edge[p] = make_int2(s4.x | (et4.x << 17), d4.x);
    p = atomicAdd(&g_cursor[d4.y], 1); g_edge[p] = make_int2(s4.y | (et4.y << 17), d4.y);
    p = atomicAdd(&g_cursor[d4.z], 1); g_edge[p] = make_int2(s4.z | (et4.z << 17), d4.z);
    p = atomicAdd(&g_cursor[d4.w], 1); g_edge[p] = make_int2(s4.w | (et4.w << 17), d4.w);
}

// ---------------- K4: register-tiled SGEMM feat = x @ fc_w^T + el/er + ee ----
__global__ __launch_bounds__(256) void feat_kernel(
        const float* __restrict__ x,
        const float* __restrict__ fc_w,
        const float* __restrict__ attn_l,
        const float* __restrict__ attn_r,
        const float* __restrict__ edge_emb,
        const float* __restrict__ fc_e_w,
        const float* __restrict__ attn_e) {
    extern __shared__ float smem[];
    float* xs = smem;                              // [FBLK][IN_FEATS]
    float* wt = smem + FBLK * IN_FEATS;            // [IN_FEATS][HD]
    float* al = wt + IN_FEATS * HD;                // [HD]
    float* ar = al + HD;                           // [HD]

    int tid = threadIdx.x;
    int tx = tid & 15;
    int ty = tid >> 4;

    // ee[t][h] table: computed once by block 0's first warp
    if (blockIdx.x == 0 && tid < NUM_ETYPES * NUM_HEADS) {
        int et = tid & (NUM_ETYPES - 1);
        int h  = tid >> 3;
        const float* emb = edge_emb + et * EDGE_FEATS;
        float s = 0.f;
        for (int fe = 0; fe < EDGE_FEATS; fe++) {
            const float* wrow = fc_e_w + (h * EDGE_FEATS + fe) * EDGE_FEATS;
            float proj = 0.f;
            #pragma unroll 8
            for (int j = 0; j < EDGE_FEATS; j++) proj += emb[j] * wrow[j];
            s += proj * attn_e[h * EDGE_FEATS + fe];
        }
        g_ee[et * NUM_HEADS + h] = s;
    }

    // load fc_w transposed: fc_w[j*128+k] -> wt[k*HD+j]
    for (int i = tid; i < HD * IN_FEATS; i += 256) {
        int j = i >> 7, k = i & 127;
        wt[k * HD + j] = fc_w[i];
    }
    if (tid < HD) { al[tid] = attn_l[tid]; ar[tid] = attn_r[tid]; }

    // load 128 node rows, float4-coalesced; OOB nodes read row 0 (stores guarded)
    long long nbase = (long long)blockIdx.x * FBLK;
    for (int i = tid; i < FBLK * (IN_FEATS / 4); i += 256) {
        int n = i >> 5, k4 = i & 31;
        long long gn = nbase + n;
        const float4* srcp = (const float4*)(x + (gn < N_NODES ? gn : 0) * IN_FEATS);
        ((float4*)(xs + n * IN_FEATS))[k4] = srcp[k4];
    }
    __syncthreads();

    float acc[8][4];
    #pragma unroll
    for (int i = 0; i < 8; i++)
        #pragma unroll
        for (int c = 0; c < 4; c++) acc[i][c] = 0.f;

    #pragma unroll 2
    for (int k4 = 0; k4 < IN_FEATS / 4; k4++) {
        float4 wv0 = *(const float4*)&wt[(k4 * 4 + 0) * HD + tx * 4];
        float4 wv1 = *(const float4*)&wt[(k4 * 4 + 1) * HD + tx * 4];
        float4 wv2 = *(const float4*)&wt[(k4 * 4 + 2) * HD + tx * 4];
        float4 wv3 = *(const float4*)&wt[(k4 * 4 + 3) * HD + tx * 4];
        #pragma unroll
        for (int i = 0; i < 8; i++) {
            float4 xv = ((const float4*)(xs + (ty * 8 + i) * IN_FEATS))[k4];
            acc[i][0] = fmaf(xv.x, wv0.x, acc[i][0]);
            acc[i][1] = fmaf(xv.x, wv0.y, acc[i][1]);
            acc[i][2] = fmaf(xv.x, wv0.z, acc[i][2]);
            acc[i][3] = fmaf(xv.x, wv0.w, acc[i][3]);
            acc[i][0] = fmaf(xv.y, wv1.x, acc[i][0]);
            acc[i][1] = fmaf(xv.y, wv1.y, acc[i][1]);
            acc[i][2] = fmaf(xv.y, wv1.z, acc[i][2]);
            acc[i][3] = fmaf(xv.y, wv1.w, acc[i][3]);
            acc[i][0] = fmaf(xv.z, wv2.x, acc[i][0]);
            acc[i][1] = fmaf(xv.z, wv2.y, acc[i][1]);
            acc[i][2] = fmaf(xv.z, wv2.z, acc[i][2]);
            acc[i][3] = fmaf(xv.z, wv2.w, acc[i][3]);
            acc[i][0] = fmaf(xv.w, wv3.x, acc[i][0]);
            acc[i][1] = fmaf(xv.w, wv3.y, acc[i][1]);
            acc[i][2] = fmaf(xv.w, wv3.z, acc[i][2]);
            acc[i][3] = fmaf(xv.w, wv3.w, acc[i][3]);
        }
    }

    // epilogue: store feat rows (float4, coalesced) + el/er dots
    float4 av = *(const float4*)&al[tx * 4];
    float4 rv = *(const float4*)&ar[tx * 4];
    int h = tx >> 2;                           // head for this thread's 4 cols
    #pragma unroll
    for (int i = 0; i < 8; i++) {
        long long n = nbase + ty * 8 + i;
        bool ok = (n < N_NODES);
        if (ok)
            *(float4*)&g_feat[n * HD + tx * 4] =
                make_float4(acc[i][0], acc[i][1], acc[i][2], acc[i][3]);
        float pl = acc[i][0] * av.x + acc[i][1] * av.y
                 + acc[i][2] * av.z + acc[i][3] * av.w;
        float pr = acc[i][0] * rv.x + acc[i][1] * rv.y
                 + acc[i][2] * rv.z + acc[i][3] * rv.w;
        pl += __shfl_xor_sync(0xFFFFFFFFu, pl, 1);
        pl += __shfl_xor_sync(0xFFFFFFFFu, pl, 2);
        pr += __shfl_xor_sync(0xFFFFFFFFu, pr, 1);
        pr += __shfl_xor_sync(0xFFFFFFFFu, pr, 2);
        if ((tx & 3) == 0 && ok) {
            g_el[n * 4 + h] = pl;
            g_er[n * 4 + h] = pr;
        }
    }
}

// ---------------- K_ex: edge-parallel exp(leaky(logit)) in CSR order ----------
__global__ __launch_bounds__(256) void ex_kernel() {
    __shared__ float see[NUM_ETYPES * NUM_HEADS];
    int tid = threadIdx.x;
    if (tid < NUM_ETYPES * NUM_HEADS) see[tid] = g_ee[tid];
    __syncthreads();

    int t = blockIdx.x * blockDim.x + tid;     // CSR edge index
    if (t >= N_EDGES) return;
    int2 ed = g_edge[t];
    int s  = ed.x & 0x1FFFF;
    int et = ed.x >> 17;
    int d  = ed.y;
    float4 el = __ldg(((const float4*)g_el) + s);
    float4 er = __ldg(((const float4*)g_er) + d);
    float e0 = el.x + er.x + see[et * 4 + 0];
    float e1 = el.y + er.y + see[et * 4 + 1];
    float e2 = el.z + er.z + see[et * 4 + 2];
    float e3 = el.w + er.w + see[et * 4 + 3];
    e0 = e0 > 0.f ? e0 : NEG_SLOPE * e0;
    e1 = e1 > 0.f ? e1 : NEG_SLOPE * e1;
    e2 = e2 > 0.f ? e2 : NEG_SLOPE * e2;
    e3 = e3 > 0.f ? e3 : NEG_SLOPE * e3;
    g_ex[t] = make_float4(__expf(e0), __expf(e1), __expf(e2), __expf(e3));
}

// ---------------- K5: per-dst gather, warp-staged edge tiles ------------------
// One warp per dst node; lane covers output cols {2*lane, 2*lane+1} (head
// lane>>3). Per 32-edge tile: coalesced int2+float4 loads (one per lane),
// ex staged to smem. Per edge: 1 shfl (src) + 1 LDS (p) + 1 scattered LDG.64.
// Pad lanes stage s=0, p=0 -> zero contribution (exact). Denom fused in-loop.
__global__ __launch_bounds__(256) void aggregate_kernel(float* __restrict__ out) {
    __shared__ float4 sh_ex[8][32];            // 4 KB
    int tid = threadIdx.x;
    int warp = tid >> 5, lane = tid & 31;
    int n = blockIdx.x * 8 + warp;
    if (n >= N_NODES) return;

    float2* out2 = (float2*)out;
    int beg = g_off[n];
    int deg = g_off[n + 1] - beg;
    if (deg == 0) {
        out2[n * 32 + lane] = make_float2(0.f, 0.f);
        return;
    }
    int hsel = lane >> 3;                      // head for this lane's 2 columns
    const float* exf = (const float*)&sh_ex[warp][0];

    float denom = 0.f;
    float2 acc = make_float2(0.f, 0.f);

    for (int tb = 0; tb < deg; tb += 32) {
        int tl = min(32, deg - tb);
        int edx = 0;
        float4 e4 = make_float4(0.f, 0.f, 0.f, 0.f);
        if (lane < tl) {
            edx = __ldg(&g_edge[beg + tb + lane].x);
            e4  = __ldg(g_ex + beg + tb + lane);
        }
        __syncwarp();
        sh_ex[warp][lane] = e4;
        __syncwarp();

        int tl_pad = (tl + 7) & ~7;            // pads contribute p=0, s=0
        for (int j = 0; j < tl_pad; j += 8) {
            int s[8]; float p[8]; float2 f[8];
            #pragma unroll
            for (int k = 0; k < 8; k++) {
                s[k] = __shfl_sync(0xFFFFFFFFu, edx, j + k) & 0x1FFFF;
                p[k] = exf[(j + k) * 4 + hsel];
            }
            #pragma unroll
            for (int k = 0; k < 8; k++)
                f[k] = __ldg(((const float2*)(g_feat + s[k] * HD)) + lane);
            #pragma unroll
            for (int k = 0; k < 8; k++) {
                denom += p[k];
                acc.x = fmaf(p[k], f[k].x, acc.x);
                acc.y = fmaf(p[k], f[k].y, acc.y);
            }
        }
    }

    float inv = 1.f / denom;
    out2[n * 32 + lane] = make_float2(acc.x * inv, acc.y * inv);
}

// ---------------- launch ------------------------------------------------------
// R11 topology (best known): side = memset/hist/scan1/scan23/scatter_lite;
// main = feat (el/er as epilogue). Join. ex, aggregate.
extern "C" void kernel_launch(void* const* d_in, const int* in_sizes, int n_in,
                              void* d_out, int out_size) {
    const float* x        = (const float*)d_in[0];
    const int*   src      = (const int*)d_in[1];
    const int*   dst      = (const int*)d_in[2];
    const int*   etype    = (const int*)d_in[3];
    const float* fc_w     = (const float*)d_in[4];
    const float* fc_e_w   = (const float*)d_in[5];
    const float* edge_emb = (const float*)d_in[6];
    const float* attn_l   = (const float*)d_in[7];
    const float* attn_r   = (const float*)d_in[8];
    const float* attn_e   = (const float*)d_in[9];
    float* out = (float*)d_out;

    static bool attr_set = false;
    if (!attr_set) {
        cudaFuncSetAttribute(feat_kernel,
                             cudaFuncAttributeMaxDynamicSharedMemorySize,
                             FEAT_SMEM_BYTES);
        attr_set = true;
    }

    void* cntPtr = nullptr;
    cudaGetSymbolAddress(&cntPtr, g_count);

    cudaStream_t side = 0;
    cudaEvent_t evFork = 0, evJoin = 0;
    bool forked =
        (cudaStreamCreateWithFlags(&side, cudaStreamNonBlocking) == cudaSuccess) &&
        (cudaEventCreateWithFlags(&evFork, cudaEventDisableTiming) == cudaSuccess) &&
        (cudaEventCreateWithFlags(&evJoin, cudaEventDisableTiming) == cudaSuccess);

    if (forked && cudaEventRecord(evFork, 0) == cudaSuccess &&
        cudaStreamWaitEvent(side, evFork, 0) == cudaSuccess) {
        // side stream: full CSR build including position scatter
        cudaMemsetAsync(cntPtr, 0, N_NODES * sizeof(int), side);
        hist_kernel<<<E4_BLOCKS, 256, 0, side>>>(dst);
        scan1_kernel<<<NSBLK, SBLK, 0, side>>>();
        scan23_kernel<<<NSBLK, SBLK, 0, side>>>();
        scatter_lite_kernel<<<E4_BLOCKS, 256, 0, side>>>(src, dst, etype);
        cudaEventRecord(evJoin, side);
        // main stream: dense projection (runs concurrently)
        feat_kernel<<<NFBLK, 256, FEAT_SMEM_BYTES>>>(x, fc_w, attn_l, attn_r,
                                                     edge_emb, fc_e_w, attn_e);
        cudaStreamWaitEvent(0, evJoin, 0);
    } else {
        // fallback: fully serial on capture stream
        cudaMemsetAsync(cntPtr, 0, N_NODES * sizeof(int), 0);
        hist_kernel<<<E4_BLOCKS, 256>>>(dst);
        scan1_kernel<<<NSBLK, SBLK>>>();
        scan23_kernel<<<NSBLK, SBLK>>>();
        scatter_lite_kernel<<<E4_BLOCKS, 256>>>(src, dst, etype);
        feat_kernel<<<NFBLK, 256, FEAT_SMEM_BYTES>>>(x, fc_w, attn_l, attn_r,
                                                     edge_emb, fc_e_w, attn_e);
    }

    ex_kernel<<<(N_EDGES + 255) / 256, 256>>>();
    aggregate_kernel<<<(N_NODES + 7) / 8, 256>>>(out);

    if (side)   cudaStreamDestroy(side);
    if (evFork) cudaEventDestroy(evFork);
    if (evJoin) cudaEventDestroy(evJoin);
}

// round 16
// speedup vs baseline: 1.3685x; 1.0400x over previous
#include <cuda_runtime.h>
#include <cuda_bf16.h>
#include <math.h>

// Problem constants (fixed by the dataset)
#define N_NODES   100000
#define N_EDGES   1600000
#define IN_FEATS  128
#define HD        64          // NUM_HEADS * OUT_FEATS = 4*16
#define NUM_HEADS 4
#define OUT_FEATS 16
#define EDGE_FEATS 32
#define NUM_ETYPES 8
#define NEG_SLOPE 0.2f

#define SBLK  512
#define NSBLK ((N_NODES + SBLK - 1) / SBLK)   // 196
#define E4    (N_EDGES / 4)                    // 400000 int4 groups
#define E4_BLOCKS ((E4 + 255) / 256)           // ceil-div grid
#define FBLK  128                              // nodes per feat block
#define NFBLK ((N_NODES + FBLK - 1) / FBLK)    // 782

// feat_kernel dynamic smem layout (floats): xs + wt + al + ar
#define FEAT_SMEM_FLOATS (FBLK * IN_FEATS + IN_FEATS * HD + 2 * HD)
#define FEAT_SMEM_BYTES  (FEAT_SMEM_FLOATS * 4)

// ---------------- static device scratch (no allocations allowed) -------------
__device__ __align__(16) float  g_feat[N_NODES * HD];     // projected features [N,64]
__device__ __align__(16) float  g_el[N_NODES * NUM_HEADS];
__device__ __align__(16) float  g_er[N_NODES * NUM_HEADS];
__device__ __align__(16) float  g_ee[NUM_ETYPES * NUM_HEADS];  // [et][h]
__device__ int    g_count[N_NODES];
__device__ int    g_off[N_NODES + 1];
__device__ int    g_cursor[N_NODES];
__device__ __align__(8) int2   g_edge[N_EDGES];           // (src|et<<17, dst), CSR order
__device__ int    g_bsum[NSBLK];

// ---------------- K1: histogram of dst (4 edges/thread, int4 loads) ---------
__global__ void hist_kernel(const int* __restrict__ dst) {
    int t = blockIdx.x * blockDim.x + threadIdx.x;
    if (t >= E4) return;
    int4 d = ((const int4*)dst)[t];
    atomicAdd(&g_count[d.x], 1);
    atomicAdd(&g_count[d.y], 1);
    atomicAdd(&g_count[d.z], 1);
    atomicAdd(&g_count[d.w], 1);
}

// ---------------- K2a: per-block inclusive scan of counts -------------------
__global__ __launch_bounds__(SBLK) void scan1_kernel() {
    __shared__ int sm[SBLK];
    int t = threadIdx.x;
    int i = blockIdx.x * SBLK + t;
    int c = (i < N_NODES) ? g_count[i] : 0;
    sm[t] = c;
    __syncthreads();
    #pragma unroll
    for (int off = 1; off < SBLK; off <<= 1) {
        int v = (t >= off) ? sm[t - off] : 0;
        __syncthreads();
        sm[t] += v;
        __syncthreads();
    }
    if (i < N_NODES) g_off[i] = sm[t] - c;     // block-local exclusive
    if (t == SBLK - 1) g_bsum[blockIdx.x] = sm[t];
}

// ---------------- K2b: merged scan of block sums + fix-up + cursor init -----
__global__ __launch_bounds__(SBLK) void scan23_kernel() {
    __shared__ int bs[SBLK];
    int t = threadIdx.x;
    int myb = g_bsum[blockIdx.x];              // read before smem scan
    bs[t] = (t < NSBLK) ? g_bsum[t] : 0;
    __syncthreads();
    #pragma unroll
    for (int off = 1; off < SBLK; off <<= 1) {
        int v = (t >= off) ? bs[t - off] : 0;
        __syncthreads();
        bs[t] += v;
        __syncthreads();
    }
    int prefix = bs[blockIdx.x] - myb;         // exclusive prefix of this block
    int i = blockIdx.x * SBLK + t;
    if (i < N_NODES) {
        int o = g_off[i] + prefix;
        g_off[i] = o;
        g_cursor[i] = o;
    }
    if (blockIdx.x == NSBLK - 1 && t == 0) g_off[N_NODES] = bs[NSBLK - 1];
}

// ---------------- K3: position-only scatter, one int2 STG.64 per edge -------
__global__ void scatter_lite_kernel(const int* __restrict__ src,
                                    const int* __restrict__ dst,
                                    const int* __restrict__ etype) {
    int t = blockIdx.x * blockDim.x + threadIdx.x;
    if (t >= E4) return;
    int4 s4  = ((const int4*)src)[t];
    int4 d4  = ((const int4*)dst)[t];
    int4 et4 = ((const int4*)etype)[t];
    int p;
    p = atomicAdd(&g_cursor[d4.x], 1); g_edge[p] = make_int2(s4.x | (et4.x << 17), d4.x);
    p = atomicAdd(&g_cursor[d4.y], 1); g_edge[p] = make_int2(s4.y | (et4.y << 17), d4.y);
    p = atomicAdd(&g_cursor[d4.z], 1); g_edge[p] = make_int2(s4.z | (et4.z << 17), d4.z);
    p = atomicAdd(&g_cursor[d4.w], 1); g_edge[p] = make_int2(s4.w | (et4.w << 17), d4.w);
}

// ---------------- K4: register-tiled SGEMM feat = x @ fc_w^T + el/er + ee ----
__global__ __launch_bounds__(256) void feat_kernel(
        const float* __restrict__ x,
        const float* __restrict__ fc_w,
        const float* __restrict__ attn_l,
        const float* __restrict__ attn_r,
        const float* __restrict__ edge_emb,
        const float* __restrict__ fc_e_w,
        const float* __restrict__ attn_e) {
    extern __shared__ float smem[];
    float* xs = smem;                              // [FBLK][IN_FEATS]
    float* wt = smem + FBLK * IN_FEATS;            // [IN_FEATS][HD]
    float* al = wt + IN_FEATS * HD;                // [HD]
    float* ar = al + HD;                           // [HD]

    int tid = threadIdx.x;
    int tx = tid & 15;
    int ty = tid >> 4;

    // ee[t][h] table: computed once by block 0's first warp
    if (blockIdx.x == 0 && tid < NUM_ETYPES * NUM_HEADS) {
        int et = tid & (NUM_ETYPES - 1);
        int h  = tid >> 3;
        const float* emb = edge_emb + et * EDGE_FEATS;
        float s = 0.f;
        for (int fe = 0; fe < EDGE_FEATS; fe++) {
            const float* wrow = fc_e_w + (h * EDGE_FEATS + fe) * EDGE_FEATS;
            float proj = 0.f;
            #pragma unroll 8
            for (int j = 0; j < EDGE_FEATS; j++) proj += emb[j] * wrow[j];
            s += proj * attn_e[h * EDGE_FEATS + fe];
        }
        g_ee[et * NUM_HEADS + h] = s;
    }

    // load fc_w transposed: fc_w[j*128+k] -> wt[k*HD+j]
    for (int i = tid; i < HD * IN_FEATS; i += 256) {
        int j = i >> 7, k = i & 127;
        wt[k * HD + j] = fc_w[i];
    }
    if (tid < HD) { al[tid] = attn_l[tid]; ar[tid] = attn_r[tid]; }

    // load 128 node rows, float4-coalesced; OOB nodes read row 0 (stores guarded)
    long long nbase = (long long)blockIdx.x * FBLK;
    for (int i = tid; i < FBLK * (IN_FEATS / 4); i += 256) {
        int n = i >> 5, k4 = i & 31;
        long long gn = nbase + n;
        const float4* srcp = (const float4*)(x + (gn < N_NODES ? gn : 0) * IN_FEATS);
        ((float4*)(xs + n * IN_FEATS))[k4] = srcp[k4];
    }
    __syncthreads();

    float acc[8][4];
    #pragma unroll
    for (int i = 0; i < 8; i++)
        #pragma unroll
        for (int c = 0; c < 4; c++) acc[i][c] = 0.f;

    #pragma unroll 2
    for (int k4 = 0; k4 < IN_FEATS / 4; k4++) {
        float4 wv0 = *(const float4*)&wt[(k4 * 4 + 0) * HD + tx * 4];
        float4 wv1 = *(const float4*)&wt[(k4 * 4 + 1) * HD + tx * 4];
        float4 wv2 = *(const float4*)&wt[(k4 * 4 + 2) * HD + tx * 4];
        float4 wv3 = *(const float4*)&wt[(k4 * 4 + 3) * HD + tx * 4];
        #pragma unroll
        for (int i = 0; i < 8; i++) {
            float4 xv = ((const float4*)(xs + (ty * 8 + i) * IN_FEATS))[k4];
            acc[i][0] = fmaf(xv.x, wv0.x, acc[i][0]);
            acc[i][1] = fmaf(xv.x, wv0.y, acc[i][1]);
            acc[i][2] = fmaf(xv.x, wv0.z, acc[i][2]);
            acc[i][3] = fmaf(xv.x, wv0.w, acc[i][3]);
            acc[i][0] = fmaf(xv.y, wv1.x, acc[i][0]);
            acc[i][1] = fmaf(xv.y, wv1.y, acc[i][1]);
            acc[i][2] = fmaf(xv.y, wv1.z, acc[i][2]);
            acc[i][3] = fmaf(xv.y, wv1.w, acc[i][3]);
            acc[i][0] = fmaf(xv.z, wv2.x, acc[i][0]);
            acc[i][1] = fmaf(xv.z, wv2.y, acc[i][1]);
            acc[i][2] = fmaf(xv.z, wv2.z, acc[i][2]);
            acc[i][3] = fmaf(xv.z, wv2.w, acc[i][3]);
            acc[i][0] = fmaf(xv.w, wv3.x, acc[i][0]);
            acc[i][1] = fmaf(xv.w, wv3.y, acc[i][1]);
            acc[i][2] = fmaf(xv.w, wv3.z, acc[i][2]);
            acc[i][3] = fmaf(xv.w, wv3.w, acc[i][3]);
        }
    }

    // epilogue: store feat rows (float4, coalesced) + el/er dots
    float4 av = *(const float4*)&al[tx * 4];
    float4 rv = *(const float4*)&ar[tx * 4];
    int h = tx >> 2;                           // head for this thread's 4 cols
    #pragma unroll
    for (int i = 0; i < 8; i++) {
        long long n = nbase + ty * 8 + i;
        bool ok = (n < N_NODES);
        if (ok)
            *(float4*)&g_feat[n * HD + tx * 4] =
                make_float4(acc[i][0], acc[i][1], acc[i][2], acc[i][3]);
        float pl = acc[i][0] * av.x + acc[i][1] * av.y
                 + acc[i][2] * av.z + acc[i][3] * av.w;
        float pr = acc[i][0] * rv.x + acc[i][1] * rv.y
                 + acc[i][2] * rv.z + acc[i][3] * rv.w;
        pl += __shfl_xor_sync(0xFFFFFFFFu, pl, 1);
        pl += __shfl_xor_sync(0xFFFFFFFFu, pl, 2);
        pr += __shfl_xor_sync(0xFFFFFFFFu, pr, 1);
        pr += __shfl_xor_sync(0xFFFFFFFFu, pr, 2);
        if ((tx & 3) == 0 && ok) {
            g_el[n * 4 + h] = pl;
            g_er[n * 4 + h] = pr;
        }
    }
}

// ---------------- K5: per-dst FUSED softmax + gather --------------------------
// One warp per dst node; lane covers output cols {2*lane, 2*lane+1} (head
// lane>>3). Per 32-edge tile, lane i handles edge i's full attention math:
// coalesced edge load -> scattered el4[src] gather -> +er[n]+ee[et] ->
// leaky -> exp -> stage 4 exps to smem. Then the gather loop: 1 shfl (src)
// + 1 LDS (p) + 1 scattered LDG.64 per edge. Pad lanes stage zeros (exact).
// Denominator accumulates in-loop. No g_ex round-trip, no ex kernel.
__global__ __launch_bounds__(256) void aggregate_kernel(float* __restrict__ out) {
    __shared__ float4 sh_ex[8][32];            // 4 KB
    __shared__ float  see[NUM_ETYPES * NUM_HEADS];
    int tid = threadIdx.x;
    if (tid < NUM_ETYPES * NUM_HEADS) see[tid] = g_ee[tid];
    __syncthreads();

    int warp = tid >> 5, lane = tid & 31;
    int n = blockIdx.x * 8 + warp;
    if (n >= N_NODES) return;

    float2* out2 = (float2*)out;
    int beg = g_off[n];
    int deg = g_off[n + 1] - beg;
    if (deg == 0) {
        out2[n * 32 + lane] = make_float2(0.f, 0.f);
        return;
    }
    int hsel = lane >> 3;                      // head for this lane's 2 columns
    float4 ern = __ldg(((const float4*)g_er) + n);
    const float* exf = (const float*)&sh_ex[warp][0];

    float denom = 0.f;
    float2 acc = make_float2(0.f, 0.f);

    for (int tb = 0; tb < deg; tb += 32) {
        int tl = min(32, deg - tb);
        int edx = 0;
        float4 e4 = make_float4(0.f, 0.f, 0.f, 0.f);
        if (lane < tl) {
            edx = __ldg(&g_edge[beg + tb + lane].x);
            int s  = edx & 0x1FFFF;
            int et = edx >> 17;
            float4 el = __ldg(((const float4*)g_el) + s);
            float e0 = el.x + ern.x + see[et * 4 + 0];
            float e1 = el.y + ern.y + see[et * 4 + 1];
            float e2 = el.z + ern.z + see[et * 4 + 2];
            float e3 = el.w + ern.w + see[et * 4 + 3];
            e0 = e0 > 0.f ? e0 : NEG_SLOPE * e0;
            e1 = e1 > 0.f ? e1 : NEG_SLOPE * e1;
            e2 = e2 > 0.f ? e2 : NEG_SLOPE * e2;
            e3 = e3 > 0.f ? e3 : NEG_SLOPE * e3;
            e4 = make_float4(__expf(e0), __expf(e1), __expf(e2), __expf(e3));
        }
        __syncwarp();
        sh_ex[warp][lane] = e4;
        __syncwarp();

        int tl_pad = (tl + 7) & ~7;            // pads contribute p=0, s=0
        for (int j = 0; j < tl_pad; j += 8) {
            int s[8]; float p[8]; float2 f[8];
            #pragma unroll
            for (int k = 0; k < 8; k++) {
                s[k] = __shfl_sync(0xFFFFFFFFu, edx, j + k) & 0x1FFFF;
                p[k] = exf[(j + k) * 4 + hsel];
            }
            #pragma unroll
            for (int k = 0; k < 8; k++)
                f[k] = __ldg(((const float2*)(g_feat + s[k] * HD)) + lane);
            #pragma unroll
            for (int k = 0; k < 8; k++) {
                denom += p[k];
                acc.x = fmaf(p[k], f[k].x, acc.x);
                acc.y = fmaf(p[k], f[k].y, acc.y);
            }
        }
    }

    float inv = 1.f / denom;
    out2[n * 32 + lane] = make_float2(acc.x * inv, acc.y * inv);
}

// ---------------- launch ------------------------------------------------------
// R11 topology: side = memset/hist/scan1/scan23/scatter_lite; main = feat
// (el/er as epilogue). Join. Fused aggregate (ex folded in).
extern "C" void kernel_launch(void* const* d_in, const int* in_sizes, int n_in,
                              void* d_out, int out_size) {
    const float* x        = (const float*)d_in[0];
    const int*   src      = (const int*)d_in[1];
    const int*   dst      = (const int*)d_in[2];
    const int*   etype    = (const int*)d_in[3];
    const float* fc_w     = (const float*)d_in[4];
    const float* fc_e_w   = (const float*)d_in[5];
    const float* edge_emb = (const float*)d_in[6];
    const float* attn_l   = (const float*)d_in[7];
    const float* attn_r   = (const float*)d_in[8];
    const float* attn_e   = (const float*)d_in[9];
    float* out = (float*)d_out;

    static bool attr_set = false;
    if (!attr_set) {
        cudaFuncSetAttribute(feat_kernel,
                             cudaFuncAttributeMaxDynamicSharedMemorySize,
                             FEAT_SMEM_BYTES);
        attr_set = true;
    }

    void* cntPtr = nullptr;
    cudaGetSymbolAddress(&cntPtr, g_count);

    cudaStream_t side = 0;
    cudaEvent_t evFork = 0, evJoin = 0;
    bool forked =
        (cudaStreamCreateWithFlags(&side, cudaStreamNonBlocking) == cudaSuccess) &&
        (cudaEventCreateWithFlags(&evFork, cudaEventDisableTiming) == cudaSuccess) &&
        (cudaEventCreateWithFlags(&evJoin, cudaEventDisableTiming) == cudaSuccess);

    if (forked && cudaEventRecord(evFork, 0) == cudaSuccess &&
        cudaStreamWaitEvent(side, evFork, 0) == cudaSuccess) {
        // side stream: full CSR build including position scatter
        cudaMemsetAsync(cntPtr, 0, N_NODES * sizeof(int), side);
        hist_kernel<<<E4_BLOCKS, 256, 0, side>>>(dst);
        scan1_kernel<<<NSBLK, SBLK, 0, side>>>();
        scan23_kernel<<<NSBLK, SBLK, 0, side>>>();
        scatter_lite_kernel<<<E4_BLOCKS, 256, 0, side>>>(src, dst, etype);
        cudaEventRecord(evJoin, side);
        // main stream: dense projection (runs concurrently)
        feat_kernel<<<NFBLK, 256, FEAT_SMEM_BYTES>>>(x, fc_w, attn_l, attn_r,
                                                     edge_emb, fc_e_w, attn_e);
        cudaStreamWaitEvent(0, evJoin, 0);
    } else {
        // fallback: fully serial on capture stream
        cudaMemsetAsync(cntPtr, 0, N_NODES * sizeof(int), 0);
        hist_kernel<<<E4_BLOCKS, 256>>>(dst);
        scan1_kernel<<<NSBLK, SBLK>>>();
        scan23_kernel<<<NSBLK, SBLK>>>();
        scatter_lite_kernel<<<E4_BLOCKS, 256>>>(src, dst, etype);
        feat_kernel<<<NFBLK, 256, FEAT_SMEM_BYTES>>>(x, fc_w, attn_l, attn_r,
                                                     edge_emb, fc_e_w, attn_e);
    }

    aggregate_kernel<<<(N_NODES + 7) / 8, 256>>>(out);

    if (side)   cudaStreamDestroy(side);
    if (evFork) cudaEventDestroy(evFork);
    if (evJoin) cudaEventDestroy(evJoin);
}